// round 11
// baseline (speedup 1.0000x reference)
#include <cuda_runtime.h>
#include <cuda_bf16.h>
#include <cstdint>

// ---------------- arch-feature gate ----------------
#if defined(__CUDA_ARCH_FEAT_SM103_ALL) || defined(__CUDA_ARCH_FEAT_SM100_ALL) || \
    defined(__CUDA_ARCH_FEAT_SM101_ALL) ||                                        \
    (defined(__CUDA_ARCH_SPECIFIC__) && (__CUDA_ARCH_SPECIFIC__ >= 1000))
#define HAS_TCGEN05 1
#else
#define HAS_TCGEN05 0
#endif

// ---------------- problem/tiling ----------------
// out[f, hw] = relu( sum_c W[f,c] * X[c,hw] + b[f] ),  F=C=512, HW=65536.
// Proven geometry: A = X^T (M=hw=256, 2 atoms, K-major), B = W (N=f=256, K-major).
// K=512 in 16 chunks of 32; 3 passes: Ah*Bh + Ah*Bl + Al*Bh (bf16 split of fp32).
// R11: 512 threads (halved producer/epilogue serial sections) + single-thread
// fence.proxy.async (was executed by all warps every chunk).
#define NCHUNK 16
#define NSTAGE 2
#define NTHREADS 512

// Prepacked W (1 MB): g_WP[ch][f][128B row = hi bf16 c(32) | lo bf16 c(32)],
// pre-SW128-swizzled by f%8, chunk-major.
__device__ __align__(128) unsigned char g_WP[16ull * 512ull * 128ull];

// ---------------- smem layout (main kernel) ----------------
// 0: tmem ptr | 16+16s: full[s] | 24+16s: empty[s] | 64: done | 128: bias(1KB)
// 4096 + s*65536 : stage s { A(X^T) 32KB | B(W) 32KB }
// 135168 + b*32768 : Xs fp32 staging buffers [32 c][256 hw], b = ch&1
#define STAGE0   4096
#define STAGE_SZ 65536
#define A_OFF    0
#define B_OFF    32768
#define XS_OFF   (STAGE0 + NSTAGE * STAGE_SZ)     // 135168
#define BIAS_OFF 128
#define SMEM_TOTAL (XS_OFF + 2 * 32768)           // 200704
#define MBAR_FULL(s)  (16u + 16u * (s))
#define MBAR_EMPTY(s) (24u + 16u * (s))
#define MBAR_DONE     64u

// idesc kind::f16 (proven): dtype=F32(b4), atype=BF16(b7), btype=BF16(b10),
// N=256 -> 32<<17, M=128 -> 8<<24
static constexpr unsigned IDESC =
    (1u << 4) | (1u << 7) | (1u << 10) | (32u << 17) | (8u << 24);

__device__ __forceinline__ uint32_t smem_u32(const void* p) {
    uint32_t a;
    asm("{ .reg .u64 t; cvta.to.shared.u64 t, %1; cvt.u32.u64 %0, t; }" : "=r"(a) : "l"(p));
    return a;
}
__device__ __forceinline__ uint32_t pack_lo_bf16x2(float x0, float x1) {
    __nv_bfloat162 p = __floats2bfloat162_rn(x0, x1);
    return *reinterpret_cast<uint32_t*>(&p);
}

#if HAS_TCGEN05
__device__ __forceinline__ void mbar_init(uint32_t a, uint32_t cnt) {
    asm volatile("mbarrier.init.shared.b64 [%0], %1;" :: "r"(a), "r"(cnt) : "memory");
}
__device__ __forceinline__ void mbar_arrive(uint32_t a) {
    asm volatile("mbarrier.arrive.shared.b64 _, [%0];" :: "r"(a) : "memory");
}
__device__ __forceinline__ void mbar_wait(uint32_t a, uint32_t parity) {
    asm volatile(
        "{\n\t.reg .pred P;\n\t"
        "WL%=:\n\t"
        "mbarrier.try_wait.parity.acquire.cta.shared::cta.b64 P, [%0], %1, 0x989680;\n\t"
        "@!P bra WL%=;\n\t}"
        :: "r"(a), "r"(parity) : "memory");
}
__device__ __forceinline__ void expect_tx(uint32_t a, uint32_t bytes) {
    asm volatile("mbarrier.arrive.expect_tx.shared.b64 _, [%0], %1;"
                 :: "r"(a), "r"(bytes) : "memory");
}
__device__ __forceinline__ void bulk_g2s(uint32_t dst, uint64_t gsrc,
                                         uint32_t bytes, uint32_t mbar) {
    asm volatile(
        "cp.async.bulk.shared::cluster.global.mbarrier::complete_tx::bytes "
        "[%0], [%1], %2, [%3];"
        :: "r"(dst), "l"(gsrc), "r"(bytes), "r"(mbar) : "memory");
}
// K-major SW128 desc (proven): layout=2, version=1, SBO=64, LBO=1
__device__ __forceinline__ uint64_t sw128_desc_k(uint32_t addr) {
    return (2ull << 61) | (1ull << 46) | (64ull << 32) | (1ull << 16) |
           ((uint64_t)(addr >> 4) & 0x3FFFull);
}
__device__ __forceinline__ void mma_ss(uint32_t d, uint64_t ad, uint64_t bd, uint32_t en) {
    asm volatile(
        "{\n\t.reg .pred p;\n\tsetp.ne.u32 p, %4, 0;\n\t"
        "tcgen05.mma.cta_group::1.kind::f16 [%0], %1, %2, %3, {%5,%5,%5,%5}, p;\n\t}"
        :: "r"(d), "l"(ad), "l"(bd), "r"(IDESC), "r"(en), "r"(0u) : "memory");
}
__device__ __forceinline__ void mma_commit(uint32_t mbar) {
    asm volatile(
        "tcgen05.commit.cta_group::1.mbarrier::arrive::one.shared::cluster.b64 [%0];"
        :: "r"(mbar) : "memory");
}
__device__ __forceinline__ void ldtm_x32(uint32_t* r, uint32_t a) {
    asm volatile(
        "tcgen05.ld.sync.aligned.32x32b.x32.b32 "
        "{%0, %1, %2, %3, %4, %5, %6, %7, "
        " %8, %9, %10, %11, %12, %13, %14, %15, "
        " %16, %17, %18, %19, %20, %21, %22, %23, "
        " %24, %25, %26, %27, %28, %29, %30, %31}, [%32];"
        : "=r"(r[0]),  "=r"(r[1]),  "=r"(r[2]),  "=r"(r[3]),
          "=r"(r[4]),  "=r"(r[5]),  "=r"(r[6]),  "=r"(r[7]),
          "=r"(r[8]),  "=r"(r[9]),  "=r"(r[10]), "=r"(r[11]),
          "=r"(r[12]), "=r"(r[13]), "=r"(r[14]), "=r"(r[15]),
          "=r"(r[16]), "=r"(r[17]), "=r"(r[18]), "=r"(r[19]),
          "=r"(r[20]), "=r"(r[21]), "=r"(r[22]), "=r"(r[23]),
          "=r"(r[24]), "=r"(r[25]), "=r"(r[26]), "=r"(r[27]),
          "=r"(r[28]), "=r"(r[29]), "=r"(r[30]), "=r"(r[31])
        : "r"(a));
}
#endif  // HAS_TCGEN05

// =====================================================================
// W prepass (~6us): g_WP[ch][f][128B: hi 32c | lo 32c], swizzled by f%8.
// =====================================================================
__global__ void __launch_bounds__(256) wprep_kernel(const float* __restrict__ W) {
    int item = blockIdx.x * 256 + threadIdx.x;   // 8192 items
    int f = item >> 4;
    int ch = item & 15;
    const float* wr = W + (size_t)f * 512 + ch * 32;
    float v[32];
    #pragma unroll
    for (int i = 0; i < 8; i++)
        *reinterpret_cast<float4*>(v + 4 * i) =
            *reinterpret_cast<const float4*>(wr + 4 * i);
    uint32_t hi[16], lo[16];
    #pragma unroll
    for (int p = 0; p < 16; p++) {
        uint32_t u0 = __float_as_uint(v[2 * p]), u1 = __float_as_uint(v[2 * p + 1]);
        hi[p] = __byte_perm(u0, u1, 0x7632);
        lo[p] = pack_lo_bf16x2(v[2 * p]     - __uint_as_float(u0 & 0xFFFF0000u),
                               v[2 * p + 1] - __uint_as_float(u1 & 0xFFFF0000u));
    }
    unsigned char* row = g_WP + (size_t)ch * 65536 + (size_t)f * 128;
    int r7 = f & 7;
    #pragma unroll
    for (int j = 0; j < 4; j++)
        *reinterpret_cast<uint4*>(row + ((j ^ r7) * 16)) =
            make_uint4(hi[4 * j], hi[4 * j + 1], hi[4 * j + 2], hi[4 * j + 3]);
    #pragma unroll
    for (int j = 0; j < 4; j++)
        *reinterpret_cast<uint4*>(row + (((j + 4) ^ r7) * 16)) =
            make_uint4(lo[4 * j], lo[4 * j + 1], lo[4 * j + 2], lo[4 * j + 3]);
}

// =====================================================================
// Main GEMM. grid=512 x 512 threads: f0=(bid&1)*256, hw0=(bid>>1)*256.
// =====================================================================
__global__ void __launch_bounds__(NTHREADS, 1)
spconv_kernel(const float* __restrict__ X, const float* __restrict__ W,
              const float* __restrict__ bias, float* __restrict__ out)
{
    extern __shared__ char smem[];
    const int tid = threadIdx.x;
    const int f0  = (blockIdx.x & 1) * 256;
    const int hw0 = (blockIdx.x >> 1) * 256;

#if HAS_TCGEN05
    const uint32_t sb = smem_u32(smem);
    const int wid = tid >> 5;
    const int lane = tid & 31;

    if (wid == 0) {
        asm volatile("tcgen05.alloc.cta_group::1.sync.aligned.shared::cta.b32 [%0], %1;"
                     :: "r"(sb), "r"(512u) : "memory");
        asm volatile("tcgen05.relinquish_alloc_permit.cta_group::1.sync.aligned;" ::: "memory");
    }
    if (tid == 0) {
        #pragma unroll
        for (int s = 0; s < NSTAGE; s++) {
            mbar_init(sb + MBAR_FULL(s), NTHREADS + 1);  // thread arrives + expect_tx
            mbar_init(sb + MBAR_EMPTY(s), 1);            // mma commit
        }
        mbar_init(sb + MBAR_DONE, 1);
    }
    if (tid < 256)
        reinterpret_cast<float*>(smem + BIAS_OFF)[tid] = bias[f0 + tid];
    __syncthreads();
    uint32_t tmem;
    asm volatile("ld.shared.b32 %0, [%1];" : "=r"(tmem) : "r"(sb));

    uint64_t wg;
    asm("cvta.to.global.u64 %0, %1;" : "=l"(wg) : "l"((const void*)g_WP));
    wg += (uint64_t)f0 * 128;

    // X load geometry: 4 float4s/thread; c = 8*i + (tid>>6), q = tid&63.
    const int xc = tid >> 6;            // 0..7
    const int xq = tid & 63;            // 0..63
    const float* xbase = X + (size_t)xc * 65536 + hw0 + xq * 4;

    // prefetch chunk 0
    float4 pf[4];
    #pragma unroll
    for (int i = 0; i < 4; i++)
        pf[i] = *reinterpret_cast<const float4*>(xbase + (size_t)(8 * i) * 65536);

    int pst = 0, pph = 1;   // producer cursor (first empty-wait passes)
    for (int ch = 0; ch < NCHUNK; ch++) {
        mbar_wait(sb + MBAR_EMPTY(pst), (uint32_t)pph);
        char* stg = smem + STAGE0 + pst * STAGE_SZ;
        const uint32_t stb = sb + STAGE0 + pst * STAGE_SZ;
        float* Xs = reinterpret_cast<float*>(smem + XS_OFF + (ch & 1) * 32768);

        // ---- B = W: bulk copy prepacked 32KB ----
        if (tid == 0) {
            expect_tx(sb + MBAR_FULL(pst), 32768u);
            bulk_g2s(stb + B_OFF, wg + (uint64_t)ch * 65536ull, 32768u,
                     sb + MBAR_FULL(pst));
        }

        // ---- drain prefetched fp32 X into staging buffer ----
        #pragma unroll
        for (int i = 0; i < 4; i++)
            *reinterpret_cast<float4*>(&Xs[(xc + 8 * i) * 256 + xq * 4]) = pf[i];
        __syncthreads();    // Xs[ch&1] fully written; prior converts all done

        // ---- prefetch NEXT chunk ----
        if (ch + 1 < NCHUNK) {
            #pragma unroll
            for (int i = 0; i < 4; i++)
                pf[i] = *reinterpret_cast<const float4*>(
                    xbase + (size_t)((ch + 1) * 32 + 8 * i) * 65536);
        }

        // ---- transpose + convert: thread owns (hw row, c half) ----
        {
            const int hwl = tid & 255;      // hw row
            const int h   = tid >> 8;       // c half: c in [16h, 16h+16)
            float v[16];
            #pragma unroll
            for (int j = 0; j < 16; j++)
                v[j] = Xs[(h * 16 + j) * 256 + hwl];   // conflict-free LDS
            uint32_t hi[8], lo[8];
            #pragma unroll
            for (int p = 0; p < 8; p++) {
                uint32_t u0 = __float_as_uint(v[2 * p]);
                uint32_t u1 = __float_as_uint(v[2 * p + 1]);
                hi[p] = __byte_perm(u0, u1, 0x7632);
                lo[p] = pack_lo_bf16x2(
                    v[2 * p]     - __uint_as_float(u0 & 0xFFFF0000u),
                    v[2 * p + 1] - __uint_as_float(u1 & 0xFFFF0000u));
            }
            unsigned char* row = reinterpret_cast<unsigned char*>(stg + A_OFF) +
                                 (size_t)hwl * 128;
            const int r7 = hwl & 7;
            #pragma unroll
            for (int j = 0; j < 2; j++)       // hi: 16B units h*2+j
                *reinterpret_cast<uint4*>(row + (((h * 2 + j) ^ r7) * 16)) =
                    make_uint4(hi[4 * j], hi[4 * j + 1], hi[4 * j + 2], hi[4 * j + 3]);
            #pragma unroll
            for (int j = 0; j < 2; j++)       // lo: 16B units 4+h*2+j
                *reinterpret_cast<uint4*>(row + (((4 + h * 2 + j) ^ r7) * 16)) =
                    make_uint4(lo[4 * j], lo[4 * j + 1], lo[4 * j + 2], lo[4 * j + 3]);
        }

        mbar_arrive(sb + MBAR_FULL(pst));     // release: orders this thread's STS

        // ---- MMA issue (tid 32 only; single fence AFTER acquire-wait) ----
        if (tid == 32) {
            mbar_wait(sb + MBAR_FULL(pst), (uint32_t)(pph ^ 1));
            asm volatile("fence.proxy.async.shared::cta;" ::: "memory");
            uint64_t ad = sw128_desc_k(stb + A_OFF);
            uint64_t bd = sw128_desc_k(stb + B_OFF);
            #pragma unroll
            for (int a = 0; a < 2; a++) {        // hw M-atoms (128 rows each)
                uint64_t ada = ad + a * 1024;    // +16KB
                uint32_t d = tmem + a * 256;
                #pragma unroll
                for (int k = 0; k < 2; k++) {    // K=16 steps (hi @ +0, lo @ +4)
                    uint64_t ah = ada + k * 2, al = ada + 4 + k * 2;
                    uint64_t bh = bd + k * 2,  bl = bd + 4 + k * 2;
                    mma_ss(d, ah, bh, (ch == 0 && k == 0) ? 0u : 1u);
                    mma_ss(d, ah, bl, 1u);
                    mma_ss(d, al, bh, 1u);
                }
            }
            mma_commit(sb + MBAR_EMPTY(pst));
            if (ch == NCHUNK - 1) mma_commit(sb + MBAR_DONE);
        }

        if (++pst == NSTAGE) { pst = 0; pph ^= 1; }
    }

    // ---- epilogue: 16 warps, each 4 column-blocks (transpose-free) ----
    mbar_wait(sb + MBAR_DONE, 0u);
    asm volatile("tcgen05.fence::after_thread_sync;" ::: "memory");

    const float* bias_s = reinterpret_cast<const float*>(smem + BIAS_OFF);
    const int atom = (wid >> 2) & 1;             // hw half (M-atom)
    const int sub  = wid & 3;                    // TMEM subpartition (= wid%4)
    const int cbh  = wid >> 3;                   // column half (0: cols 0-127, 1: 128-255)
    const int hw   = hw0 + atom * 128 + sub * 32 + lane;
    #pragma unroll
    for (int cb = 0; cb < 4; cb++) {
        uint32_t col = (uint32_t)(cbh * 128 + cb * 32);
        uint32_t r[32];
        ldtm_x32(r, tmem + atom * 256 + col);
        asm volatile("tcgen05.wait::ld.sync.aligned;" ::: "memory");
        float* op = out + (size_t)(f0 + col) * 65536 + hw;
        #pragma unroll
        for (int j = 0; j < 32; j++) {
            float v = __uint_as_float(r[j]) + bias_s[col + j];
            op[(size_t)j * 65536] = fmaxf(v, 0.0f);
        }
    }

    __syncthreads();
    if (wid == 0) {
        asm volatile("tcgen05.dealloc.cta_group::1.sync.aligned.b32 %0, %1;"
                     :: "r"(tmem), "r"(512u));
    }

#else
    // ========= FFMA fallback (plain pass; never executes on GB300) =========
    if (tid < 256) {
        float* Xsf = reinterpret_cast<float*>(smem + STAGE0);          // [32][128]
        float* Wsf = reinterpret_cast<float*>(smem + STAGE0 + 16384);  // [256][32]
        const int hw0b = (blockIdx.x >> 1) * 256;
        const int tx = tid & 15, ty = tid >> 4;
        for (int half = 0; half < 2; half++) {
            const int hwb = hw0b + half * 128;
            const int hw_l = tx * 8, f_l = ty * 16;
            float acc[16][8];
            #pragma unroll
            for (int i = 0; i < 16; i++)
                #pragma unroll
                for (int j = 0; j < 8; j++) acc[i][j] = 0.0f;
            for (int ch = 0; ch < 16; ch++) {
                const int c0 = ch * 32;
                #pragma unroll
                for (int i = 0; i < 4; i++) {
                    int l = tid + 256 * i, row = l >> 5, c4 = l & 31;
                    *reinterpret_cast<float4*>(&Xsf[row * 128 + c4 * 4]) =
                        *reinterpret_cast<const float4*>(
                            &X[(size_t)(c0 + row) * 65536 + hwb + c4 * 4]);
                }
                #pragma unroll
                for (int i = 0; i < 8; i++) {
                    int l = tid + 256 * i, row = l >> 3, c4 = l & 7;
                    *reinterpret_cast<float4*>(&Wsf[row * 32 + c4 * 4]) =
                        *reinterpret_cast<const float4*>(
                            &W[(size_t)(f0 + row) * 512 + c0 + c4 * 4]);
                }
                __syncthreads();
                #pragma unroll 4
                for (int c = 0; c < 32; c++) {
                    float xv[8];
                    *reinterpret_cast<float4*>(xv) =
                        *reinterpret_cast<float4*>(&Xsf[c * 128 + hw_l]);
                    *reinterpret_cast<float4*>(xv + 4) =
                        *reinterpret_cast<float4*>(&Xsf[c * 128 + hw_l + 4]);
                    #pragma unroll
                    for (int i = 0; i < 16; i++) {
                        float wv = Wsf[(f_l + i) * 32 + c];
                        #pragma unroll
                        for (int j = 0; j < 8; j++) acc[i][j] += wv * xv[j];
                    }
                }
                __syncthreads();
            }
            #pragma unroll
            for (int i = 0; i < 16; i++) {
                float b = bias[f0 + f_l + i];
                float* op = out + (size_t)(f0 + f_l + i) * 65536 + hwb + hw_l;
                #pragma unroll
                for (int j = 0; j < 8; j++)
                    op[j] = fmaxf(acc[i][j] + b, 0.0f);
            }
        }
    } else {
        // idle half-block still participates in barriers
        for (int it = 0; it < 16 * 2 * 2; it++) __syncthreads();
    }
#endif
}

extern "C" void kernel_launch(void* const* d_in, const int* in_sizes, int n_in,
                              void* d_out, int out_size) {
    const float* X = (const float*)d_in[0];      // [1,512,256,256]
    const float* W = (const float*)d_in[1];      // [512,512] (already masked)
    const float* bias = (const float*)d_in[n_in - 1];
    for (int i = 1; i < n_in; i++)
        if (in_sizes[i] == 512) { bias = (const float*)d_in[i]; break; }
    float* out = (float*)d_out;

    static bool attr_done = false;
    if (!attr_done) {
        cudaFuncSetAttribute(spconv_kernel,
                             cudaFuncAttributeMaxDynamicSharedMemorySize, SMEM_TOTAL);
        attr_done = true;
    }

    wprep_kernel<<<32, 256>>>(W);
    spconv_kernel<<<512, NTHREADS, SMEM_TOTAL>>>(X, W, bias, out);
}

// round 12
// speedup vs baseline: 1.4350x; 1.4350x over previous
#include <cuda_runtime.h>
#include <cuda_bf16.h>
#include <cstdint>

// ---------------- arch-feature gate ----------------
#if defined(__CUDA_ARCH_FEAT_SM103_ALL) || defined(__CUDA_ARCH_FEAT_SM100_ALL) || \
    defined(__CUDA_ARCH_FEAT_SM101_ALL) ||                                        \
    (defined(__CUDA_ARCH_SPECIFIC__) && (__CUDA_ARCH_SPECIFIC__ >= 1000))
#define HAS_TCGEN05 1
#else
#define HAS_TCGEN05 0
#endif

// ---------------- problem/tiling ----------------
// out[f, hw] = relu( sum_c W[f,c] * X[c,hw] + b[f] ),  F=C=512, HW=65536.
// 2-CTA cluster cg2 MMA: cluster tile = D[hw=256 (M, split 128/CTA), f=512
// (2 dispatches of N=256, B split per CTA)]. A = X^T K-major (each CTA converts
// its own 128 hw rows ONCE chip-wide). K=512 in 16 chunks of 32; 3 passes:
// Ah*Bh + Ah*Bl + Al*Bh (bf16 split of fp32) — proven numerics.
#define NCHUNK 16
#define NSTAGE 3
#define NTHREADS 512

// Prepacked W (1 MB): g_WP[ch][rank][disp][fr][128B row = hi bf16 c32 | lo c32],
// global f = disp*256 + rank*128 + fr, pre-SW128-swizzled by fr%8.
__device__ __align__(128) unsigned char g_WP[16ull * 512ull * 128ull];

// ---------------- smem layout (main kernel) ----------------
// 0: tmem ptr | 16+16s: FULL[s] | 64+16s: EMPTY[s] | 112+16s: PEER[s] | 160: DONE
// 2048: bias (512 floats, 2KB)
// 4096 + s*49152 : stage s { A(X^T,128x128B) 16KB | B(W, 2 disp x 128x128B) 32KB }
// 151552 + b*16384 : Xs fp32 staging [32 c][128 hw], b = ch&1
#define STAGE0   4096
#define STAGE_SZ 49152
#define A_OFF    0
#define B_OFF    16384
#define XS_OFF   (STAGE0 + NSTAGE * STAGE_SZ)     // 151552
#define BIAS_OFF 2048
#define SMEM_TOTAL (XS_OFF + 2 * 16384)           // 184320
#define MBAR_FULL(s)  (16u + 16u * (s))
#define MBAR_EMPTY(s) (64u + 16u * (s))
#define MBAR_PEER(s)  (112u + 16u * (s))
#define MBAR_DONE     160u

// idesc kind::f16 cg2 (example-proven fields): dtype=F32(b4), atype=BF16(b7),
// btype=BF16(b10), N=256 -> 32<<17, M_TOTAL=256 -> 16<<24
static constexpr unsigned IDESC =
    (1u << 4) | (1u << 7) | (1u << 10) | (32u << 17) | (16u << 24);

__device__ __forceinline__ uint32_t smem_u32(const void* p) {
    uint32_t a;
    asm("{ .reg .u64 t; cvta.to.shared.u64 t, %1; cvt.u32.u64 %0, t; }" : "=r"(a) : "l"(p));
    return a;
}
__device__ __forceinline__ uint32_t pack_lo_bf16x2(float x0, float x1) {
    __nv_bfloat162 p = __floats2bfloat162_rn(x0, x1);
    return *reinterpret_cast<uint32_t*>(&p);
}

#if HAS_TCGEN05
__device__ __forceinline__ uint32_t ctarank() {
    uint32_t r;
    asm("mov.u32 %0, %%cluster_ctarank;" : "=r"(r));
    return r;
}
__device__ __forceinline__ void cluster_sync() {
    asm volatile("barrier.cluster.arrive.aligned;" ::: "memory");
    asm volatile("barrier.cluster.wait.aligned;" ::: "memory");
}
__device__ __forceinline__ void mbar_init(uint32_t a, uint32_t cnt) {
    asm volatile("mbarrier.init.shared.b64 [%0], %1;" :: "r"(a), "r"(cnt) : "memory");
}
__device__ __forceinline__ void mbar_arrive(uint32_t a) {
    asm volatile("mbarrier.arrive.shared.b64 _, [%0];" :: "r"(a) : "memory");
}
// arrive on cluster rank 0's barrier at the same smem offset
__device__ __forceinline__ void mbar_arrive_rank0(uint32_t a) {
    asm volatile(
        "{\n\t.reg .b32 rem;\n\t"
        "mapa.shared::cluster.u32 rem, %0, 0;\n\t"
        "mbarrier.arrive.shared::cluster.b64 _, [rem];\n\t}"
        :: "r"(a) : "memory");
}
__device__ __forceinline__ void mbar_wait(uint32_t a, uint32_t parity) {
    asm volatile(
        "{\n\t.reg .pred P;\n\t"
        "WL%=:\n\t"
        "mbarrier.try_wait.parity.acquire.cta.shared::cta.b64 P, [%0], %1, 0x989680;\n\t"
        "@!P bra WL%=;\n\t}"
        :: "r"(a), "r"(parity) : "memory");
}
__device__ __forceinline__ void expect_tx(uint32_t a, uint32_t bytes) {
    asm volatile("mbarrier.arrive.expect_tx.shared.b64 _, [%0], %1;"
                 :: "r"(a), "r"(bytes) : "memory");
}
__device__ __forceinline__ void bulk_g2s(uint32_t dst, uint64_t gsrc,
                                         uint32_t bytes, uint32_t mbar) {
    asm volatile(
        "cp.async.bulk.shared::cluster.global.mbarrier::complete_tx::bytes "
        "[%0], [%1], %2, [%3];"
        :: "r"(dst), "l"(gsrc), "r"(bytes), "r"(mbar) : "memory");
}
// K-major SW128 desc (proven): layout=2, version=1, SBO=64, LBO=1
__device__ __forceinline__ uint64_t sw128_desc_k(uint32_t addr) {
    return (2ull << 61) | (1ull << 46) | (64ull << 32) | (1ull << 16) |
           ((uint64_t)(addr >> 4) & 0x3FFFull);
}
// cg2 bf16 SS MMA (example-proven form)
__device__ __forceinline__ void mma_ss_cg2(uint32_t d, uint64_t ad, uint64_t bd,
                                           uint32_t en) {
    asm volatile(
        "{\n\t.reg .pred p;\n\tsetp.ne.u32 p, %5, 0;\n\t"
        "tcgen05.mma.cta_group::2.kind::f16 [%0], %1, %2, %3, "
        "{%4, %4, %4, %4, %4, %4, %4, %4}, p;\n\t}"
        :: "r"(d), "l"(ad), "l"(bd), "r"(IDESC), "r"(0u), "r"(en) : "memory");
}
__device__ __forceinline__ void mma_commit_mc2(uint32_t mbar) {
    asm volatile(
        "tcgen05.commit.cta_group::2.mbarrier::arrive::one.shared::cluster"
        ".multicast::cluster.b64 [%0], %1;"
        :: "r"(mbar), "h"((uint16_t)0x3) : "memory");
}
__device__ __forceinline__ void ldtm_x32(uint32_t* r, uint32_t a) {
    asm volatile(
        "tcgen05.ld.sync.aligned.32x32b.x32.b32 "
        "{%0, %1, %2, %3, %4, %5, %6, %7, "
        " %8, %9, %10, %11, %12, %13, %14, %15, "
        " %16, %17, %18, %19, %20, %21, %22, %23, "
        " %24, %25, %26, %27, %28, %29, %30, %31}, [%32];"
        : "=r"(r[0]),  "=r"(r[1]),  "=r"(r[2]),  "=r"(r[3]),
          "=r"(r[4]),  "=r"(r[5]),  "=r"(r[6]),  "=r"(r[7]),
          "=r"(r[8]),  "=r"(r[9]),  "=r"(r[10]), "=r"(r[11]),
          "=r"(r[12]), "=r"(r[13]), "=r"(r[14]), "=r"(r[15]),
          "=r"(r[16]), "=r"(r[17]), "=r"(r[18]), "=r"(r[19]),
          "=r"(r[20]), "=r"(r[21]), "=r"(r[22]), "=r"(r[23]),
          "=r"(r[24]), "=r"(r[25]), "=r"(r[26]), "=r"(r[27]),
          "=r"(r[28]), "=r"(r[29]), "=r"(r[30]), "=r"(r[31])
        : "r"(a));
}
#endif  // HAS_TCGEN05

// =====================================================================
// W prepass (~6us): g_WP[ch][rank][disp][fr][128B], f = disp*256+rank*128+fr.
// =====================================================================
__global__ void __launch_bounds__(256) wprep_kernel(const float* __restrict__ W) {
    int item = blockIdx.x * 256 + threadIdx.x;   // 8192 items
    int f = item >> 4;
    int ch = item & 15;
    int disp = f >> 8;
    int rank = (f >> 7) & 1;
    int fr = f & 127;
    const float* wr = W + (size_t)f * 512 + ch * 32;
    float v[32];
    #pragma unroll
    for (int i = 0; i < 8; i++)
        *reinterpret_cast<float4*>(v + 4 * i) =
            *reinterpret_cast<const float4*>(wr + 4 * i);
    uint32_t hi[16], lo[16];
    #pragma unroll
    for (int p = 0; p < 16; p++) {
        uint32_t u0 = __float_as_uint(v[2 * p]), u1 = __float_as_uint(v[2 * p + 1]);
        hi[p] = __byte_perm(u0, u1, 0x7632);
        lo[p] = pack_lo_bf16x2(v[2 * p]     - __uint_as_float(u0 & 0xFFFF0000u),
                               v[2 * p + 1] - __uint_as_float(u1 & 0xFFFF0000u));
    }
    unsigned char* row = g_WP +
        ((((size_t)ch * 2 + rank) * 2 + disp) * 128 + fr) * 128;
    int r7 = fr & 7;
    #pragma unroll
    for (int j = 0; j < 4; j++)
        *reinterpret_cast<uint4*>(row + ((j ^ r7) * 16)) =
            make_uint4(hi[4 * j], hi[4 * j + 1], hi[4 * j + 2], hi[4 * j + 3]);
    #pragma unroll
    for (int j = 0; j < 4; j++)
        *reinterpret_cast<uint4*>(row + (((j + 4) ^ r7) * 16)) =
            make_uint4(lo[4 * j], lo[4 * j + 1], lo[4 * j + 2], lo[4 * j + 3]);
}

// =====================================================================
// Main GEMM. grid=512, clusters of 2. hw0=(bid>>1)*256; rank owns hw rows
// hw0+rank*128..+128 and B halves for both f dispatches.
// =====================================================================
__global__ void __launch_bounds__(NTHREADS, 1) __cluster_dims__(2, 1, 1)
spconv_kernel(const float* __restrict__ X, const float* __restrict__ W,
              const float* __restrict__ bias, float* __restrict__ out)
{
    extern __shared__ char smem[];
    const int tid = threadIdx.x;

#if HAS_TCGEN05
    const uint32_t sb = smem_u32(smem);
    const int wid = tid >> 5;
    const int lane = tid & 31;
    const uint32_t rank = ctarank();
    const int hw0 = (blockIdx.x >> 1) * 256;
    const int hwA0 = hw0 + (int)rank * 128;      // this CTA's A rows

    if (wid == 0) {
        asm volatile("tcgen05.alloc.cta_group::2.sync.aligned.shared::cta.b32 [%0], %1;"
                     :: "r"(sb), "r"(512u) : "memory");
        asm volatile("tcgen05.relinquish_alloc_permit.cta_group::2.sync.aligned;" ::: "memory");
    }
    if (tid == 0) {
        #pragma unroll
        for (int s = 0; s < NSTAGE; s++) {
            mbar_init(sb + MBAR_FULL(s), NTHREADS + 1);  // threads + expect_tx
            mbar_init(sb + MBAR_EMPTY(s), 1);            // multicast commit
            mbar_init(sb + MBAR_PEER(s), 1);             // rank1 cluster-arrive
        }
        mbar_init(sb + MBAR_DONE, 1);
    }
    reinterpret_cast<float*>(smem + BIAS_OFF)[tid] = bias[tid];  // all 512 f
    __syncthreads();
    cluster_sync();                               // barriers visible cluster-wide
    uint32_t tmem;
    asm volatile("ld.shared.b32 %0, [%1];" : "=r"(tmem) : "r"(sb));

    uint64_t wg;
    asm("cvta.to.global.u64 %0, %1;" : "=l"(wg) : "l"((const void*)g_WP));
    wg += (uint64_t)rank * 32768;                 // [ch][rank][disp][fr]

    // X load geometry: 2 float4/thread; xc = tid>>5 (0..15), rows xc and xc+16.
    const int xc = tid >> 5;
    const int xq = tid & 31;
    const float* xbase = X + hwA0 + xq * 4;

    // prefetch chunk 0
    float4 pf0 = *reinterpret_cast<const float4*>(xbase + (size_t)xc * 65536);
    float4 pf1 = *reinterpret_cast<const float4*>(xbase + (size_t)(xc + 16) * 65536);

    int pst = 0, pph = 1;
    for (int ch = 0; ch < NCHUNK; ch++) {
        mbar_wait(sb + MBAR_EMPTY(pst), (uint32_t)pph);
        char* stg = smem + STAGE0 + pst * STAGE_SZ;
        const uint32_t stb = sb + STAGE0 + pst * STAGE_SZ;
        float* Xs = reinterpret_cast<float*>(smem + XS_OFF + (ch & 1) * 16384);

        // ---- B = W halves: one contiguous 32KB bulk ----
        if (tid == 0) {
            expect_tx(sb + MBAR_FULL(pst), 32768u);
            bulk_g2s(stb + B_OFF, wg + (uint64_t)ch * 65536ull, 32768u,
                     sb + MBAR_FULL(pst));
        }

        // ---- drain prefetched fp32 X into staging [32 c][128 hw] ----
        *reinterpret_cast<float4*>(&Xs[xc * 128 + xq * 4]) = pf0;
        *reinterpret_cast<float4*>(&Xs[(xc + 16) * 128 + xq * 4]) = pf1;
        __syncthreads();

        // ---- prefetch NEXT chunk ----
        if (ch + 1 < NCHUNK) {
            pf0 = *reinterpret_cast<const float4*>(
                xbase + (size_t)((ch + 1) * 32 + xc) * 65536);
            pf1 = *reinterpret_cast<const float4*>(
                xbase + (size_t)((ch + 1) * 32 + xc + 16) * 65536);
        }

        // ---- transpose + convert: thread owns (hw row, 8-c octet) ----
        {
            const int hwl = tid & 127;
            const int h   = tid >> 7;             // c in [8h, 8h+8)
            float v[8];
            #pragma unroll
            for (int j = 0; j < 8; j++)
                v[j] = Xs[(h * 8 + j) * 128 + hwl];  // conflict-free
            uint32_t hi[4], lo[4];
            #pragma unroll
            for (int p = 0; p < 4; p++) {
                uint32_t u0 = __float_as_uint(v[2 * p]);
                uint32_t u1 = __float_as_uint(v[2 * p + 1]);
                hi[p] = __byte_perm(u0, u1, 0x7632);
                lo[p] = pack_lo_bf16x2(
                    v[2 * p]     - __uint_as_float(u0 & 0xFFFF0000u),
                    v[2 * p + 1] - __uint_as_float(u1 & 0xFFFF0000u));
            }
            unsigned char* row = reinterpret_cast<unsigned char*>(stg + A_OFF) +
                                 (size_t)hwl * 128;
            const int r7 = hwl & 7;
            *reinterpret_cast<uint4*>(row + ((h ^ r7) * 16)) =
                make_uint4(hi[0], hi[1], hi[2], hi[3]);
            *reinterpret_cast<uint4*>(row + (((4 + h) ^ r7) * 16)) =
                make_uint4(lo[0], lo[1], lo[2], lo[3]);
        }

        mbar_arrive(sb + MBAR_FULL(pst));

        if (tid == 32) {
            if (rank == 1) {
                // rank1: own tile ready -> signal leader
                mbar_wait(sb + MBAR_FULL(pst), (uint32_t)(pph ^ 1));
                asm volatile("fence.proxy.async.shared::cta;" ::: "memory");
                mbar_arrive_rank0(sb + MBAR_PEER(pst));
            } else {
                // leader: wait own tile + peer tile, issue cg2 MMAs
                mbar_wait(sb + MBAR_FULL(pst), (uint32_t)(pph ^ 1));
                mbar_wait(sb + MBAR_PEER(pst), (uint32_t)(pph ^ 1));
                asm volatile("fence.proxy.async.shared::cta;" ::: "memory");
                uint64_t ad = sw128_desc_k(stb + A_OFF);
                #pragma unroll
                for (int disp = 0; disp < 2; disp++) {   // f halves (N=256)
                    uint64_t bd = sw128_desc_k(stb + B_OFF + disp * 16384);
                    uint32_t d = tmem + disp * 256;
                    #pragma unroll
                    for (int k = 0; k < 2; k++) {        // K=16 steps
                        uint64_t ah = ad + k * 2, al = ad + 4 + k * 2;
                        uint64_t bh = bd + k * 2, bl = bd + 4 + k * 2;
                        mma_ss_cg2(d, ah, bh, (ch == 0 && k == 0) ? 0u : 1u);
                        mma_ss_cg2(d, ah, bl, 1u);
                        mma_ss_cg2(d, al, bh, 1u);
                    }
                }
                mma_commit_mc2(sb + MBAR_EMPTY(pst));    // flips both CTAs
                if (ch == NCHUNK - 1) mma_commit_mc2(sb + MBAR_DONE);
            }
        }

        if (++pst == NSTAGE) { pst = 0; pph ^= 1; }
    }

    // ---- epilogue: each CTA reads its own 128 hw rows x 512 f cols ----
    mbar_wait(sb + MBAR_DONE, 0u);
    asm volatile("tcgen05.fence::after_thread_sync;" ::: "memory");

    const float* bias_s = reinterpret_cast<const float*>(smem + BIAS_OFF);
    const int sub = wid & 3;                     // TMEM subpartition
    const int cg  = wid >> 2;                    // column group (0..3)
    const int hw  = hwA0 + sub * 32 + lane;
    #pragma unroll
    for (int cb = 0; cb < 4; cb++) {
        uint32_t col = (uint32_t)(cg * 128 + cb * 32);
        uint32_t r[32];
        ldtm_x32(r, tmem + col);
        asm volatile("tcgen05.wait::ld.sync.aligned;" ::: "memory");
        float* op = out + (size_t)col * 65536 + hw;
        #pragma unroll
        for (int j = 0; j < 32; j++) {
            float v = __uint_as_float(r[j]) + bias_s[col + j];
            op[(size_t)j * 65536] = fmaxf(v, 0.0f);
        }
    }

    __syncthreads();
    cluster_sync();                               // both CTAs done reading TMEM
    if (wid == 0) {
        asm volatile("tcgen05.dealloc.cta_group::2.sync.aligned.b32 %0, %1;"
                     :: "r"(tmem), "r"(512u));
    }
    cluster_sync();

#else
    // ========= FFMA fallback (plain pass; never executes on GB300) =========
    // CTA: hw block of 128 (bid*... grid 512 -> hw0f = bid*128), all 512 f.
    float* Xsf = reinterpret_cast<float*>(smem);            // [32][128] 16KB
    float* Wsf = reinterpret_cast<float*>(smem + 16384);    // [512][32] 64KB
    const int hw0f = (int)blockIdx.x * 128;
    const int tx = tid & 15, ty = tid >> 4;      // ty 0..31
    const int hw_l = tx * 8, f_l = ty * 16;
    float acc[16][8];
    #pragma unroll
    for (int i = 0; i < 16; i++)
        #pragma unroll
        for (int j = 0; j < 8; j++) acc[i][j] = 0.0f;
    for (int ch = 0; ch < 16; ch++) {
        const int c0 = ch * 32;
        #pragma unroll
        for (int i = 0; i < 2; i++) {            // X chunk 32x128
            int l = tid + 512 * i, row = l >> 5, c4 = l & 31;
            *reinterpret_cast<float4*>(&Xsf[row * 128 + c4 * 4]) =
                *reinterpret_cast<const float4*>(
                    &X[(size_t)(c0 + row) * 65536 + hw0f + c4 * 4]);
        }
        #pragma unroll
        for (int i = 0; i < 8; i++) {            // W chunk 512x32
            int l = tid + 512 * i, row = l >> 3, c4 = l & 7;
            *reinterpret_cast<float4*>(&Wsf[row * 32 + c4 * 4]) =
                *reinterpret_cast<const float4*>(
                    &W[(size_t)row * 512 + c0 + c4 * 4]);
        }
        __syncthreads();
        #pragma unroll 4
        for (int c = 0; c < 32; c++) {
            float xv[8];
            *reinterpret_cast<float4*>(xv) =
                *reinterpret_cast<float4*>(&Xsf[c * 128 + hw_l]);
            *reinterpret_cast<float4*>(xv + 4) =
                *reinterpret_cast<float4*>(&Xsf[c * 128 + hw_l + 4]);
            #pragma unroll
            for (int i = 0; i < 16; i++) {
                float wv = Wsf[(f_l + i) * 32 + c];
                #pragma unroll
                for (int j = 0; j < 8; j++) acc[i][j] += wv * xv[j];
            }
        }
        __syncthreads();
    }
    #pragma unroll
    for (int i = 0; i < 16; i++) {
        float b = bias[f_l + i];
        float* op = out + (size_t)(f_l + i) * 65536 + hw0f + hw_l;
        #pragma unroll
        for (int j = 0; j < 8; j++)
            op[j] = fmaxf(acc[i][j] + b, 0.0f);
    }
#endif
}

extern "C" void kernel_launch(void* const* d_in, const int* in_sizes, int n_in,
                              void* d_out, int out_size) {
    const float* X = (const float*)d_in[0];      // [1,512,256,256]
    const float* W = (const float*)d_in[1];      // [512,512] (already masked)
    const float* bias = (const float*)d_in[n_in - 1];
    for (int i = 1; i < n_in; i++)
        if (in_sizes[i] == 512) { bias = (const float*)d_in[i]; break; }
    float* out = (float*)d_out;

    static bool attr_done = false;
    if (!attr_done) {
        cudaFuncSetAttribute(spconv_kernel,
                             cudaFuncAttributeMaxDynamicSharedMemorySize, SMEM_TOTAL);
        attr_done = true;
    }

    wprep_kernel<<<32, 256>>>(W);
    spconv_kernel<<<512, NTHREADS, SMEM_TOTAL>>>(X, W, bias, out);
}

// round 13
// speedup vs baseline: 1.4395x; 1.0032x over previous
#include <cuda_runtime.h>
#include <cuda_bf16.h>
#include <cstdint>

// ---------------- arch-feature gate ----------------
#if defined(__CUDA_ARCH_FEAT_SM103_ALL) || defined(__CUDA_ARCH_FEAT_SM100_ALL) || \
    defined(__CUDA_ARCH_FEAT_SM101_ALL) ||                                        \
    (defined(__CUDA_ARCH_SPECIFIC__) && (__CUDA_ARCH_SPECIFIC__ >= 1000))
#define HAS_TCGEN05 1
#else
#define HAS_TCGEN05 0
#endif

// ---------------- problem/tiling ----------------
// out[f, hw] = relu( sum_c W[f,c] * X[c,hw] + b[f] ),  F=C=512, HW=65536.
// 2-CTA cluster cg2 MMA: cluster tile D[hw=256 (M, 128/CTA), f=512 (2 disp of
// N=256, B split per CTA)]. A = X^T K-major, converted ONCE chip-wide.
// K=512 in 16 chunks of 32; 3 passes: Ah*Bh + Ah*Bl + Al*Bh (bf16 split).
// R13: warp-specialized MMA issuer (warp 16) decoupled from producer lockstep.
#define NCHUNK 16
#define NSTAGE 3
#define NTHREADS 544          // 512 producers (warps 0-15) + MMA warp (16)
#define PRODS 512

// Prepacked W (1 MB): g_WP[ch][rank][disp][fr][128B row = hi bf16 c32 | lo c32],
// f = disp*256 + rank*128 + fr, pre-SW128-swizzled by fr%8.
__device__ __align__(128) unsigned char g_WP[16ull * 512ull * 128ull];

// ---------------- smem layout ----------------
#define STAGE0   4096
#define STAGE_SZ 49152
#define A_OFF    0
#define B_OFF    16384
#define XS_OFF   (STAGE0 + NSTAGE * STAGE_SZ)     // 151552
#define BIAS_OFF 2048
#define SMEM_TOTAL (XS_OFF + 2 * 16384)           // 184320
#define MBAR_FULL(s)  (16u + 16u * (s))
#define MBAR_EMPTY(s) (64u + 16u * (s))
#define MBAR_PEER(s)  (112u + 16u * (s))
#define MBAR_DONE     160u

// idesc kind::f16 cg2 (proven): dtype=F32(b4), atype=BF16(b7), btype=BF16(b10),
// N=256 -> 32<<17, M_TOTAL=256 -> 16<<24
static constexpr unsigned IDESC =
    (1u << 4) | (1u << 7) | (1u << 10) | (32u << 17) | (16u << 24);

__device__ __forceinline__ uint32_t smem_u32(const void* p) {
    uint32_t a;
    asm("{ .reg .u64 t; cvta.to.shared.u64 t, %1; cvt.u32.u64 %0, t; }" : "=r"(a) : "l"(p));
    return a;
}
__device__ __forceinline__ uint32_t pack_lo_bf16x2(float x0, float x1) {
    __nv_bfloat162 p = __floats2bfloat162_rn(x0, x1);
    return *reinterpret_cast<uint32_t*>(&p);
}

#if HAS_TCGEN05
__device__ __forceinline__ uint32_t ctarank() {
    uint32_t r;
    asm("mov.u32 %0, %%cluster_ctarank;" : "=r"(r));
    return r;
}
__device__ __forceinline__ void cluster_sync() {
    asm volatile("barrier.cluster.arrive.aligned;" ::: "memory");
    asm volatile("barrier.cluster.wait.aligned;" ::: "memory");
}
__device__ __forceinline__ void mbar_init(uint32_t a, uint32_t cnt) {
    asm volatile("mbarrier.init.shared.b64 [%0], %1;" :: "r"(a), "r"(cnt) : "memory");
}
__device__ __forceinline__ void mbar_arrive(uint32_t a) {
    asm volatile("mbarrier.arrive.shared.b64 _, [%0];" :: "r"(a) : "memory");
}
__device__ __forceinline__ void mbar_arrive_rank0(uint32_t a) {
    asm volatile(
        "{\n\t.reg .b32 rem;\n\t"
        "mapa.shared::cluster.u32 rem, %0, 0;\n\t"
        "mbarrier.arrive.shared::cluster.b64 _, [rem];\n\t}"
        :: "r"(a) : "memory");
}
__device__ __forceinline__ void mbar_wait(uint32_t a, uint32_t parity) {
    asm volatile(
        "{\n\t.reg .pred P;\n\t"
        "WL%=:\n\t"
        "mbarrier.try_wait.parity.acquire.cta.shared::cta.b64 P, [%0], %1, 0x989680;\n\t"
        "@!P bra WL%=;\n\t}"
        :: "r"(a), "r"(parity) : "memory");
}
__device__ __forceinline__ void expect_tx(uint32_t a, uint32_t bytes) {
    asm volatile("mbarrier.arrive.expect_tx.shared.b64 _, [%0], %1;"
                 :: "r"(a), "r"(bytes) : "memory");
}
__device__ __forceinline__ void bulk_g2s(uint32_t dst, uint64_t gsrc,
                                         uint32_t bytes, uint32_t mbar) {
    asm volatile(
        "cp.async.bulk.shared::cluster.global.mbarrier::complete_tx::bytes "
        "[%0], [%1], %2, [%3];"
        :: "r"(dst), "l"(gsrc), "r"(bytes), "r"(mbar) : "memory");
}
__device__ __forceinline__ uint64_t sw128_desc_k(uint32_t addr) {
    return (2ull << 61) | (1ull << 46) | (64ull << 32) | (1ull << 16) |
           ((uint64_t)(addr >> 4) & 0x3FFFull);
}
__device__ __forceinline__ void mma_ss_cg2(uint32_t d, uint64_t ad, uint64_t bd,
                                           uint32_t en) {
    asm volatile(
        "{\n\t.reg .pred p;\n\tsetp.ne.u32 p, %5, 0;\n\t"
        "tcgen05.mma.cta_group::2.kind::f16 [%0], %1, %2, %3, "
        "{%4, %4, %4, %4, %4, %4, %4, %4}, p;\n\t}"
        :: "r"(d), "l"(ad), "l"(bd), "r"(IDESC), "r"(0u), "r"(en) : "memory");
}
__device__ __forceinline__ void mma_commit_mc2(uint32_t mbar) {
    asm volatile(
        "tcgen05.commit.cta_group::2.mbarrier::arrive::one.shared::cluster"
        ".multicast::cluster.b64 [%0], %1;"
        :: "r"(mbar), "h"((uint16_t)0x3) : "memory");
}
__device__ __forceinline__ void ldtm_x32(uint32_t* r, uint32_t a) {
    asm volatile(
        "tcgen05.ld.sync.aligned.32x32b.x32.b32 "
        "{%0, %1, %2, %3, %4, %5, %6, %7, "
        " %8, %9, %10, %11, %12, %13, %14, %15, "
        " %16, %17, %18, %19, %20, %21, %22, %23, "
        " %24, %25, %26, %27, %28, %29, %30, %31}, [%32];"
        : "=r"(r[0]),  "=r"(r[1]),  "=r"(r[2]),  "=r"(r[3]),
          "=r"(r[4]),  "=r"(r[5]),  "=r"(r[6]),  "=r"(r[7]),
          "=r"(r[8]),  "=r"(r[9]),  "=r"(r[10]), "=r"(r[11]),
          "=r"(r[12]), "=r"(r[13]), "=r"(r[14]), "=r"(r[15]),
          "=r"(r[16]), "=r"(r[17]), "=r"(r[18]), "=r"(r[19]),
          "=r"(r[20]), "=r"(r[21]), "=r"(r[22]), "=r"(r[23]),
          "=r"(r[24]), "=r"(r[25]), "=r"(r[26]), "=r"(r[27]),
          "=r"(r[28]), "=r"(r[29]), "=r"(r[30]), "=r"(r[31])
        : "r"(a));
}
#endif  // HAS_TCGEN05

// =====================================================================
// W prepass (~6us): g_WP[ch][rank][disp][fr][128B].
// =====================================================================
__global__ void __launch_bounds__(256) wprep_kernel(const float* __restrict__ W) {
    int item = blockIdx.x * 256 + threadIdx.x;   // 8192 items
    int f = item >> 4;
    int ch = item & 15;
    int disp = f >> 8;
    int rank = (f >> 7) & 1;
    int fr = f & 127;
    const float* wr = W + (size_t)f * 512 + ch * 32;
    float v[32];
    #pragma unroll
    for (int i = 0; i < 8; i++)
        *reinterpret_cast<float4*>(v + 4 * i) =
            *reinterpret_cast<const float4*>(wr + 4 * i);
    uint32_t hi[16], lo[16];
    #pragma unroll
    for (int p = 0; p < 16; p++) {
        uint32_t u0 = __float_as_uint(v[2 * p]), u1 = __float_as_uint(v[2 * p + 1]);
        hi[p] = __byte_perm(u0, u1, 0x7632);
        lo[p] = pack_lo_bf16x2(v[2 * p]     - __uint_as_float(u0 & 0xFFFF0000u),
                               v[2 * p + 1] - __uint_as_float(u1 & 0xFFFF0000u));
    }
    unsigned char* row = g_WP +
        ((((size_t)ch * 2 + rank) * 2 + disp) * 128 + fr) * 128;
    int r7 = fr & 7;
    #pragma unroll
    for (int j = 0; j < 4; j++)
        *reinterpret_cast<uint4*>(row + ((j ^ r7) * 16)) =
            make_uint4(hi[4 * j], hi[4 * j + 1], hi[4 * j + 2], hi[4 * j + 3]);
    #pragma unroll
    for (int j = 0; j < 4; j++)
        *reinterpret_cast<uint4*>(row + (((j + 4) ^ r7) * 16)) =
            make_uint4(lo[4 * j], lo[4 * j + 1], lo[4 * j + 2], lo[4 * j + 3]);
}

// =====================================================================
// Main GEMM. grid=512 (clusters of 2), 544 threads.
// =====================================================================
__global__ void __launch_bounds__(NTHREADS, 1) __cluster_dims__(2, 1, 1)
spconv_kernel(const float* __restrict__ X, const float* __restrict__ W,
              const float* __restrict__ bias, float* __restrict__ out)
{
    extern __shared__ char smem[];
    const int tid = threadIdx.x;

#if HAS_TCGEN05
    const uint32_t sb = smem_u32(smem);
    const int wid = tid >> 5;
    const int lane = tid & 31;
    const uint32_t rank = ctarank();
    const int hw0 = (blockIdx.x >> 1) * 256;
    const int hwA0 = hw0 + (int)rank * 128;      // this CTA's A rows

    if (wid == 0) {
        asm volatile("tcgen05.alloc.cta_group::2.sync.aligned.shared::cta.b32 [%0], %1;"
                     :: "r"(sb), "r"(512u) : "memory");
        asm volatile("tcgen05.relinquish_alloc_permit.cta_group::2.sync.aligned;" ::: "memory");
    }
    if (tid == 0) {
        #pragma unroll
        for (int s = 0; s < NSTAGE; s++) {
            mbar_init(sb + MBAR_FULL(s), PRODS + 1);     // producers + expect_tx
            mbar_init(sb + MBAR_EMPTY(s), 1);            // multicast commit
            mbar_init(sb + MBAR_PEER(s), 1);             // rank1 cluster-arrive
        }
        mbar_init(sb + MBAR_DONE, 1);
    }
    if (tid < PRODS)
        reinterpret_cast<float*>(smem + BIAS_OFF)[tid] = bias[tid];
    __syncthreads();
    cluster_sync();                               // barriers visible cluster-wide
    uint32_t tmem;
    asm volatile("ld.shared.b32 %0, [%1];" : "=r"(tmem) : "r"(sb));

    if (tid < PRODS) {
        // ================= producer warps 0-15 =================
        uint64_t wg;
        asm("cvta.to.global.u64 %0, %1;" : "=l"(wg) : "l"((const void*)g_WP));
        wg += (uint64_t)rank * 32768;             // [ch][rank][disp][fr]

        const int xc = tid >> 5;                  // 0..15
        const int xq = tid & 31;                  // 0..31
        const float* xbase = X + hwA0 + xq * 4;

        float4 pf0 = *reinterpret_cast<const float4*>(xbase + (size_t)xc * 65536);
        float4 pf1 = *reinterpret_cast<const float4*>(xbase + (size_t)(xc + 16) * 65536);

        int pst = 0, pph = 1;
        for (int ch = 0; ch < NCHUNK; ch++) {
            mbar_wait(sb + MBAR_EMPTY(pst), (uint32_t)pph);
            char* stg = smem + STAGE0 + pst * STAGE_SZ;
            const uint32_t stb = sb + STAGE0 + pst * STAGE_SZ;
            float* Xs = reinterpret_cast<float*>(smem + XS_OFF + (ch & 1) * 16384);

            if (tid == 0) {
                expect_tx(sb + MBAR_FULL(pst), 32768u);
                bulk_g2s(stb + B_OFF, wg + (uint64_t)ch * 65536ull, 32768u,
                         sb + MBAR_FULL(pst));
            }

            // drain prefetched fp32 X into staging [32 c][128 hw]
            *reinterpret_cast<float4*>(&Xs[xc * 128 + xq * 4]) = pf0;
            *reinterpret_cast<float4*>(&Xs[(xc + 16) * 128 + xq * 4]) = pf1;
            asm volatile("bar.sync 1, %0;" :: "r"(PRODS) : "memory");

            if (ch + 1 < NCHUNK) {
                pf0 = *reinterpret_cast<const float4*>(
                    xbase + (size_t)((ch + 1) * 32 + xc) * 65536);
                pf1 = *reinterpret_cast<const float4*>(
                    xbase + (size_t)((ch + 1) * 32 + xc + 16) * 65536);
            }

            // transpose + convert: thread owns (hw row, 8-c octet)
            {
                const int hwl = tid & 127;
                const int h   = tid >> 7;         // c in [8h, 8h+8)
                float v[8];
                #pragma unroll
                for (int j = 0; j < 8; j++)
                    v[j] = Xs[(h * 8 + j) * 128 + hwl];
                uint32_t hi[4], lo[4];
                #pragma unroll
                for (int p = 0; p < 4; p++) {
                    uint32_t u0 = __float_as_uint(v[2 * p]);
                    uint32_t u1 = __float_as_uint(v[2 * p + 1]);
                    hi[p] = __byte_perm(u0, u1, 0x7632);
                    lo[p] = pack_lo_bf16x2(
                        v[2 * p]     - __uint_as_float(u0 & 0xFFFF0000u),
                        v[2 * p + 1] - __uint_as_float(u1 & 0xFFFF0000u));
                }
                unsigned char* row = reinterpret_cast<unsigned char*>(stg + A_OFF) +
                                     (size_t)hwl * 128;
                const int r7 = hwl & 7;
                *reinterpret_cast<uint4*>(row + ((h ^ r7) * 16)) =
                    make_uint4(hi[0], hi[1], hi[2], hi[3]);
                *reinterpret_cast<uint4*>(row + (((4 + h) ^ r7) * 16)) =
                    make_uint4(lo[0], lo[1], lo[2], lo[3]);
            }

            mbar_arrive(sb + MBAR_FULL(pst));
            if (++pst == NSTAGE) { pst = 0; pph ^= 1; }
        }
    } else if (tid == PRODS) {
        // ================= dedicated MMA thread (warp 16, lane 0) ==========
        int cst = 0, cph = 0;
        for (int ch = 0; ch < NCHUNK; ch++) {
            const uint32_t stb = sb + STAGE0 + cst * STAGE_SZ;
            if (rank == 1) {
                mbar_wait(sb + MBAR_FULL(cst), (uint32_t)cph);
                asm volatile("fence.proxy.async.shared::cta;" ::: "memory");
                mbar_arrive_rank0(sb + MBAR_PEER(cst));
            } else {
                mbar_wait(sb + MBAR_FULL(cst), (uint32_t)cph);
                mbar_wait(sb + MBAR_PEER(cst), (uint32_t)cph);
                asm volatile("fence.proxy.async.shared::cta;" ::: "memory");
                uint64_t ad = sw128_desc_k(stb + A_OFF);
                #pragma unroll
                for (int disp = 0; disp < 2; disp++) {   // f halves (N=256)
                    uint64_t bd = sw128_desc_k(stb + B_OFF + disp * 16384);
                    uint32_t d = tmem + disp * 256;
                    #pragma unroll
                    for (int k = 0; k < 2; k++) {        // K=16 steps
                        uint64_t ah = ad + k * 2, al = ad + 4 + k * 2;
                        uint64_t bh = bd + k * 2, bl = bd + 4 + k * 2;
                        mma_ss_cg2(d, ah, bh, (ch == 0 && k == 0) ? 0u : 1u);
                        mma_ss_cg2(d, ah, bl, 1u);
                        mma_ss_cg2(d, al, bh, 1u);
                    }
                }
                mma_commit_mc2(sb + MBAR_EMPTY(cst));    // flips both CTAs
                if (ch == NCHUNK - 1) mma_commit_mc2(sb + MBAR_DONE);
            }
            if (++cst == NSTAGE) { cst = 0; cph ^= 1; }
        }
    }

    // ---- epilogue: producer warps read 128 hw rows x 512 f cols ----
    if (wid < 16) {
        mbar_wait(sb + MBAR_DONE, 0u);
        asm volatile("tcgen05.fence::after_thread_sync;" ::: "memory");

        const float* bias_s = reinterpret_cast<const float*>(smem + BIAS_OFF);
        const int sub = wid & 3;                 // TMEM subpartition
        const int cg  = wid >> 2;                // column group (0..3)
        const int hw  = hwA0 + sub * 32 + lane;
        #pragma unroll
        for (int cb = 0; cb < 4; cb++) {
            uint32_t col = (uint32_t)(cg * 128 + cb * 32);
            uint32_t r[32];
            ldtm_x32(r, tmem + col);
            asm volatile("tcgen05.wait::ld.sync.aligned;" ::: "memory");
            float* op = out + (size_t)col * 65536 + hw;
            #pragma unroll
            for (int j = 0; j < 32; j++) {
                float v = __uint_as_float(r[j]) + bias_s[col + j];
                op[(size_t)j * 65536] = fmaxf(v, 0.0f);
            }
        }
    }

    __syncthreads();
    cluster_sync();                               // both CTAs done reading TMEM
    if (wid == 0) {
        asm volatile("tcgen05.dealloc.cta_group::2.sync.aligned.b32 %0, %1;"
                     :: "r"(tmem), "r"(512u));
    }
    cluster_sync();

#else
    // ========= FFMA fallback (plain pass; never executes on GB300) =========
    if (tid < 512) {
        float* Xsf = reinterpret_cast<float*>(smem);            // [32][128]
        float* Wsf = reinterpret_cast<float*>(smem + 16384);    // [512][32]
        const int hw0f = (int)blockIdx.x * 128;
        const int tx = tid & 15, ty = tid >> 4;
        const int hw_l = tx * 8, f_l = ty * 16;
        float acc[16][8];
        #pragma unroll
        for (int i = 0; i < 16; i++)
            #pragma unroll
            for (int j = 0; j < 8; j++) acc[i][j] = 0.0f;
        for (int ch = 0; ch < 16; ch++) {
            const int c0 = ch * 32;
            #pragma unroll
            for (int i = 0; i < 2; i++) {
                int l = tid + 512 * i, row = l >> 5, c4 = l & 31;
                *reinterpret_cast<float4*>(&Xsf[row * 128 + c4 * 4]) =
                    *reinterpret_cast<const float4*>(
                        &X[(size_t)(c0 + row) * 65536 + hw0f + c4 * 4]);
            }
            #pragma unroll
            for (int i = 0; i < 8; i++) {
                int l = tid + 512 * i, row = l >> 3, c4 = l & 7;
                *reinterpret_cast<float4*>(&Wsf[row * 32 + c4 * 4]) =
                    *reinterpret_cast<const float4*>(
                        &W[(size_t)row * 512 + c0 + c4 * 4]);
            }
            __syncthreads();
            #pragma unroll 4
            for (int c = 0; c < 32; c++) {
                float xv[8];
                *reinterpret_cast<float4*>(xv) =
                    *reinterpret_cast<float4*>(&Xsf[c * 128 + hw_l]);
                *reinterpret_cast<float4*>(xv + 4) =
                    *reinterpret_cast<float4*>(&Xsf[c * 128 + hw_l + 4]);
                #pragma unroll
                for (int i = 0; i < 16; i++) {
                    float wv = Wsf[(f_l + i) * 32 + c];
                    #pragma unroll
                    for (int j = 0; j < 8; j++) acc[i][j] += wv * xv[j];
                }
            }
            __syncthreads();
        }
        #pragma unroll
        for (int i = 0; i < 16; i++) {
            float b = bias[f_l + i];
            float* op = out + (size_t)(f_l + i) * 65536 + hw0f + hw_l;
            #pragma unroll
            for (int j = 0; j < 8; j++)
                op[j] = fmaxf(acc[i][j] + b, 0.0f);
        }
    } else {
        for (int it = 0; it < 32; it++) __syncthreads();
    }
#endif
}

extern "C" void kernel_launch(void* const* d_in, const int* in_sizes, int n_in,
                              void* d_out, int out_size) {
    const float* X = (const float*)d_in[0];      // [1,512,256,256]
    const float* W = (const float*)d_in[1];      // [512,512] (already masked)
    const float* bias = (const float*)d_in[n_in - 1];
    for (int i = 1; i < n_in; i++)
        if (in_sizes[i] == 512) { bias = (const float*)d_in[i]; break; }
    float* out = (float*)d_out;

    static bool attr_done = false;
    if (!attr_done) {
        cudaFuncSetAttribute(spconv_kernel,
                             cudaFuncAttributeMaxDynamicSharedMemorySize, SMEM_TOTAL);
        attr_done = true;
    }

    wprep_kernel<<<32, 256>>>(W);
    spconv_kernel<<<512, NTHREADS, SMEM_TOTAL>>>(X, W, bias, out);
}